// round 1
// baseline (speedup 1.0000x reference)
#include <cuda_runtime.h>
#include <float.h>

// Problem shape (fixed by setup_inputs): fm [B=4, C=256, H=50, W=50] f32,
// rois [R=300, 5] f32 (x0, y0, x1, y1, batch). Output [R, C, 7, 7] f32.
#define PH 7
#define PW 7
#define C_ 256
#define H_ 50
#define W_ 50
#define MAX_R 1024

struct RoiBox {
    int b;      // batch index
    int x0, y0; // top-left (rounded, clamped)
    int w, h;   // roi width/height, >= 1
};

__device__ RoiBox g_roi[MAX_R];

// Precompute integer ROI boxes once (R=300 threads; negligible cost).
// jnp.round == round-half-to-even == rintf under default RN rounding mode.
__global__ void roi_prep_kernel(const float* __restrict__ rois, int R) {
    int r = blockIdx.x * blockDim.x + threadIdx.x;
    if (r >= R) return;
    const float* p = rois + r * 5;
    float fx0 = p[0], fy0 = p[1], fx1 = p[2], fy1 = p[3], fb = p[4];
    // SPATIAL_SCALE = 1.0 -> double-scaling is identity.
    int b  = (int)fb;  // truncation, matches astype(int32)
    int x0 = min(max((int)rintf(fx0), 0), W_ - 1);
    int x1 = min(max((int)rintf(fx1), 0), W_ - 1);
    int y0 = min(max((int)rintf(fy0), 0), H_ - 1);
    int y1 = min(max((int)rintf(fy1), 0), H_ - 1);
    x1 = max(x1, x0 + 1);   // may reach W_, but loop bounds stay < W_
    y1 = max(y1, y0 + 1);
    RoiBox box;
    box.b = b; box.x0 = x0; box.y0 = y0;
    box.w = x1 - x0; box.h = y1 - y0;
    g_roi[r] = box;
}

// One thread per output element (r, c, ph, pw). Linear index -> coalesced
// stores. Bin loops read via __ldg; the whole fm (10 MB) lives in L2.
__global__ void roi_pool_kernel(const float* __restrict__ fm,
                                float* __restrict__ out,
                                int total) {
    int idx = blockIdx.x * blockDim.x + threadIdx.x;
    if (idx >= total) return;

    int pw = idx % PW;
    int t  = idx / PW;
    int ph = t % PH;
    t /= PH;
    int c  = t % C_;
    int r  = t / C_;

    RoiBox box = g_roi[r];

    // adaptive_max_pool2d bin edges:
    //   start = x0 + floor(i*w/7), end = x0 + ceil((i+1)*w/7)
    int ws = box.x0 + (pw * box.w) / PW;
    int we = box.x0 + ((pw + 1) * box.w + PW - 1) / PW;
    int hs = box.y0 + (ph * box.h) / PH;
    int he = box.y0 + ((ph + 1) * box.h + PH - 1) / PH;

    const float* base = fm + ((size_t)(box.b * C_ + c)) * (H_ * W_);

    float m = -FLT_MAX;
    for (int y = hs; y < he; ++y) {
        const float* row = base + y * W_;
        #pragma unroll 4
        for (int x = ws; x < we; ++x) {
            m = fmaxf(m, __ldg(row + x));
        }
    }
    out[idx] = m;
}

extern "C" void kernel_launch(void* const* d_in, const int* in_sizes, int n_in,
                              void* d_out, int out_size) {
    const float* fm   = (const float*)d_in[0];
    const float* rois = (const float*)d_in[1];
    float* out = (float*)d_out;

    int R = in_sizes[1] / 5;

    roi_prep_kernel<<<(R + 255) / 256, 256>>>(rois, R);

    int total = R * C_ * PH * PW;
    int threads = 256;
    int blocks = (total + threads - 1) / threads;
    roi_pool_kernel<<<blocks, threads>>>(fm, out, total);
}